// round 9
// baseline (speedup 1.0000x reference)
#include <cuda_runtime.h>
#include <cuda_bf16.h>
#include <cstring>

#define ZC 128
#define LDIM 16
#define KCODES 256
#define CDIM 8
#define NPOS 32768
#define WHPLANE 4096
#define ROWS 128           // positions per block

typedef unsigned long long u64;
typedef unsigned int u32;

#define S1f  2.0813689810056077f      // log2(e)^2
#define M2S1f (-4.1627379620112154f)  // -2*log2(e)^2

__device__ __forceinline__ u64 pk2(float lo, float hi) {
    u64 r; asm("mov.b64 %0, {%1, %2};" : "=l"(r) : "f"(lo), "f"(hi)); return r;
}
__device__ __forceinline__ u64 pk2u(u32 lo, u32 hi) {
    u64 r; asm("mov.b64 %0, {%1, %2};" : "=l"(r) : "r"(lo), "r"(hi)); return r;
}
__device__ __forceinline__ void upk2(u64 p, float& lo, float& hi) {
    asm("mov.b64 {%0, %1}, %2;" : "=f"(lo), "=f"(hi) : "l"(p));
}
__device__ __forceinline__ void upk2u(u64 p, u32& lo, u32& hi) {
    asm("mov.b64 {%0, %1}, %2;" : "=r"(lo), "=r"(hi) : "l"(p));
}
__device__ __forceinline__ u64 ffma2(u64 a, u64 b, u64 c) {
    u64 d; asm("fma.rn.f32x2 %0, %1, %2, %3;" : "=l"(d) : "l"(a), "l"(b), "l"(c)); return d;
}
__device__ __forceinline__ u64 fadd2(u64 a, u64 b) {
    u64 d; asm("add.rn.f32x2 %0, %1, %2;" : "=l"(d) : "l"(a), "l"(b)); return d;
}
__device__ __forceinline__ float sqrt_ap(float x) {
    float r; asm("sqrt.approx.f32 %0, %1;" : "=f"(r) : "f"(x)); return r;
}
__device__ __forceinline__ float ex2_ap(float x) {
    float r; asm("ex2.approx.f32 %0, %1;" : "=f"(r) : "f"(x)); return r;
}
__device__ __forceinline__ u32 cat16(__nv_bfloat16 lo, __nv_bfloat16 hi) {
    unsigned short a, b; memcpy(&a, &lo, 2); memcpy(&b, &hi, 2);
    return (u32)a | ((u32)b << 16);
}
// 3-way bf16 split: x ~= b0+b1+b2, residual ~2^-27|x|
__device__ __forceinline__ void split3(float x, __nv_bfloat16& b0, __nv_bfloat16& b1, __nv_bfloat16& b2) {
    b0 = __float2bfloat16(x);
    float r = x - __bfloat162float(b0);
    b1 = __float2bfloat16(r);
    r = r - __bfloat162float(b1);
    b2 = __float2bfloat16(r);
}
// mma.sync m16n8k16 row.col bf16 -> f32, accumulate in place
__device__ __forceinline__ void hmma(float& d0, float& d1, float& d2, float& d3,
                                     u32 a0, u32 a1, u32 a2, u32 a3, u32 b0, u32 b1) {
    asm volatile(
        "mma.sync.aligned.m16n8k16.row.col.f32.bf16.bf16.f32 "
        "{%0,%1,%2,%3}, {%4,%5,%6,%7}, {%8,%9}, {%0,%1,%2,%3};"
        : "+f"(d0), "+f"(d1), "+f"(d2), "+f"(d3)
        : "r"(a0), "r"(a1), "r"(a2), "r"(a3), "r"(b0), "r"(b1));
}

// Block: 256 threads, 8 warps. One latent l (blockIdx.y) x 128 positions.
// Warp w owns rows w*16..w*16+15. Distance GEMM G[row,code] via 3 exact
// split-bf16 HMMAs per 8-code chunk; epilogue consumes D fragments in place.
__global__ void __launch_bounds__(256, 2)
sth_mma(const float* __restrict__ z, const float* __restrict__ codes,
        float* __restrict__ out_soft, float* __restrict__ out_hard,
        float* __restrict__ out_idx)
{
    __shared__ u64   sBf[2][KCODES / 8][32];  // B frags: [variant][chunk][lane] 16 KB
    __shared__ u32   sA[ROWS][3][4];          // A data: [row][split][colpair]   6 KB
    __shared__ u64   sCC[KCODES][4];          // code f32x2 channel pairs        8 KB
    __shared__ float sCN[KCODES];             // S1*||c||^2                      1 KB
    __shared__ float sHN[ROWS];               // S1*||h||^2                      0.5 KB

    const int l    = blockIdx.y;
    const int tid  = threadIdx.x;
    const int lane = tid & 31;
    const int wid  = tid >> 5;

    // ---- preamble A: thread tid owns code k = tid ----
    {
        const float4* cp = reinterpret_cast<const float4*>(codes) + ((size_t)l * KCODES + tid) * 2;
        const float4 ca = cp[0];
        const float4 cb = cp[1];
        float c[8] = {ca.x, ca.y, ca.z, ca.w, cb.x, cb.y, cb.z, cb.w};
        u32 cs0[4], cs1[4], cs2[4];
        float cn = 0.f;
        #pragma unroll
        for (int i = 0; i < 4; i++) {
            __nv_bfloat16 x0, x1, x2, y0, y1, y2;
            split3(c[2*i],   x0, x1, x2);
            split3(c[2*i+1], y0, y1, y2);
            cs0[i] = cat16(x0, y0); cs1[i] = cat16(x1, y1); cs2[i] = cat16(x2, y2);
            cn = fmaf(c[2*i], c[2*i], cn);
            cn = fmaf(c[2*i+1], c[2*i+1], cn);
        }
        sCN[tid] = S1f * cn;
        sCC[tid][0] = pk2(c[0], c[1]); sCC[tid][1] = pk2(c[2], c[3]);
        sCC[tid][2] = pk2(c[4], c[5]); sCC[tid][3] = pk2(c[6], c[7]);
        // B fragment slots: code tid -> chunk nc = tid>>3, col-group cg = tid&7,
        // lanes cg*4+q need channel pair q: breg0 = splitX pair, breg1 = splitY pair
        const int nc = tid >> 3, cg = tid & 7;
        #pragma unroll
        for (int q = 0; q < 4; q++) {
            sBf[0][nc][cg * 4 + q] = pk2u(cs0[q], cs1[q]);  // [B0|B1]
            sBf[1][nc][cg * 4 + q] = pk2u(cs0[q], cs2[q]);  // [B0|B2]
        }
    }
    // ---- preamble B: threads 0-127 own one position row each ----
    if (tid < ROWS) {
        const int pos = blockIdx.x * ROWS + tid;
        const int bb = pos >> 12, wh = pos & 4095;
        const float* zp = z + ((size_t)bb * ZC + (size_t)l * CDIM) * WHPLANE + wh;
        float h[8];
        float hn = 0.f;
        #pragma unroll
        for (int i = 0; i < 8; i++) { h[i] = zp[i * WHPLANE]; hn = fmaf(h[i], h[i], hn); }
        sHN[tid] = S1f * hn;
        #pragma unroll
        for (int i = 0; i < 4; i++) {
            __nv_bfloat16 x0, x1, x2, y0, y1, y2;
            split3(h[2*i],   x0, x1, x2);
            split3(h[2*i+1], y0, y1, y2);
            sA[tid][0][i] = cat16(x0, y0);
            sA[tid][1][i] = cat16(x1, y1);
            sA[tid][2][i] = cat16(x2, y2);
        }
    }
    __syncthreads();

    // ---- per-thread fragment context ----
    const int q  = lane & 3;              // colpair / D col group
    const int r0 = wid * 16 + (lane >> 2);
    const int r1 = r0 + 8;
    const u32 A00 = sA[r0][0][q], A01 = sA[r0][1][q], A02 = sA[r0][2][q];
    const u32 A10 = sA[r1][0][q], A11 = sA[r1][1][q], A12 = sA[r1][2][q];
    const float hn0 = sHN[r0], hn1 = sHN[r1];

    u64 ac00 = 0ull, ac01 = 0ull, ac02 = 0ull, ac03 = 0ull;  // soft acc row r0
    u64 ac10 = 0ull, ac11 = 0ull, ac12 = 0ull, ac13 = 0ull;  // soft acc row r1
    float sume0 = 0.f, sume1 = 0.f;
    float mind0 = 3.4e38f, mind1 = 3.4e38f;
    int   mink0 = 0,        mink1 = 0;

    #pragma unroll 2
    for (int nc = 0; nc < KCODES / 8; nc++) {
        u32 b00, b01, b10, b11;
        upk2u(sBf[0][nc][lane], b00, b01);
        upk2u(sBf[1][nc][lane], b10, b11);

        float d0 = 0.f, d1 = 0.f, d2r = 0.f, d3 = 0.f;
        hmma(d0, d1, d2r, d3, A00, A10, A01, A11, b00, b01);  // [A0|A1]*[B0|B1]
        hmma(d0, d1, d2r, d3, A01, A11, A00, A10, b00, b01);  // [A1|A0]*[B0|B1]
        hmma(d0, d1, d2r, d3, A02, A12, A00, A10, b10, b11);  // [A2|A0]*[B0|B2]

        const int k0 = nc * 8 + q * 2;
        const float2 cnp = *reinterpret_cast<const float2*>(&sCN[k0]);

        // d2' = S1*||h-c||^2 (rows r0: d0,d1 ; r1: d2r,d3)
        const float e00d = fmaf(d0,  M2S1f, hn0 + cnp.x);
        const float e01d = fmaf(d1,  M2S1f, hn0 + cnp.y);
        const float e10d = fmaf(d2r, M2S1f, hn1 + cnp.x);
        const float e11d = fmaf(d3,  M2S1f, hn1 + cnp.y);

        // argmin per row (k0 before k1; cross-lane ties resolved at merge)
        bool t;
        t = e00d < mind0; mind0 = fminf(mind0, e00d); mink0 = t ? k0     : mink0;
        t = e01d < mind0; mind0 = fminf(mind0, e01d); mink0 = t ? k0 + 1 : mink0;
        t = e10d < mind1; mind1 = fminf(mind1, e10d); mink1 = t ? k0     : mink1;
        t = e11d < mind1; mind1 = fminf(mind1, e11d); mink1 = t ? k0 + 1 : mink1;

        // e = exp(-dist) = 2^(-sqrt(S1*d2))
        const float e00 = ex2_ap(0.0f - sqrt_ap(fabsf(e00d)));
        const float e01 = ex2_ap(0.0f - sqrt_ap(fabsf(e01d)));
        const float e10 = ex2_ap(0.0f - sqrt_ap(fabsf(e10d)));
        const float e11 = ex2_ap(0.0f - sqrt_ap(fabsf(e11d)));
        sume0 += (e00 + e01);
        sume1 += (e10 + e11);

        const ulonglong2* c0p = reinterpret_cast<const ulonglong2*>(sCC[k0]);
        const ulonglong2* c1p = reinterpret_cast<const ulonglong2*>(sCC[k0 + 1]);
        const ulonglong2 c0a = c0p[0], c0b = c0p[1];
        const ulonglong2 c1a = c1p[0], c1b = c1p[1];
        const u64 p00 = pk2(e00, e00), p01 = pk2(e01, e01);
        const u64 p10 = pk2(e10, e10), p11 = pk2(e11, e11);

        ac00 = ffma2(p00, c0a.x, ac00); ac01 = ffma2(p00, c0a.y, ac01);
        ac02 = ffma2(p00, c0b.x, ac02); ac03 = ffma2(p00, c0b.y, ac03);
        ac00 = ffma2(p01, c1a.x, ac00); ac01 = ffma2(p01, c1a.y, ac01);
        ac02 = ffma2(p01, c1b.x, ac02); ac03 = ffma2(p01, c1b.y, ac03);

        ac10 = ffma2(p10, c0a.x, ac10); ac11 = ffma2(p10, c0a.y, ac11);
        ac12 = ffma2(p10, c0b.x, ac12); ac13 = ffma2(p10, c0b.y, ac13);
        ac10 = ffma2(p11, c1a.x, ac10); ac11 = ffma2(p11, c1a.y, ac11);
        ac12 = ffma2(p11, c1b.x, ac12); ac13 = ffma2(p11, c1b.y, ac13);
    }

    // ---- merge across the 4 lanes sharing each row (bfly 1, 2) ----
    #pragma unroll
    for (int m = 1; m <= 2; m <<= 1) {
        sume0 += __shfl_xor_sync(0xffffffffu, sume0, m);
        sume1 += __shfl_xor_sync(0xffffffffu, sume1, m);
        {
            const float om = __shfl_xor_sync(0xffffffffu, mind0, m);
            const int   ok = __shfl_xor_sync(0xffffffffu, mink0, m);
            const bool  t  = (om < mind0) || (om == mind0 && ok < mink0);
            mind0 = t ? om : mind0; mink0 = t ? ok : mink0;
        }
        {
            const float om = __shfl_xor_sync(0xffffffffu, mind1, m);
            const int   ok = __shfl_xor_sync(0xffffffffu, mink1, m);
            const bool  t  = (om < mind1) || (om == mind1 && ok < mink1);
            mind1 = t ? om : mind1; mink1 = t ? ok : mink1;
        }
        ac00 = fadd2(ac00, __shfl_xor_sync(0xffffffffu, ac00, m));
        ac01 = fadd2(ac01, __shfl_xor_sync(0xffffffffu, ac01, m));
        ac02 = fadd2(ac02, __shfl_xor_sync(0xffffffffu, ac02, m));
        ac03 = fadd2(ac03, __shfl_xor_sync(0xffffffffu, ac03, m));
        ac10 = fadd2(ac10, __shfl_xor_sync(0xffffffffu, ac10, m));
        ac11 = fadd2(ac11, __shfl_xor_sync(0xffffffffu, ac11, m));
        ac12 = fadd2(ac12, __shfl_xor_sync(0xffffffffu, ac12, m));
        ac13 = fadd2(ac13, __shfl_xor_sync(0xffffffffu, ac13, m));
    }

    if (q == 0) {
        #pragma unroll
        for (int rr = 0; rr < 2; rr++) {
            const int   row  = rr ? r1 : r0;
            const float sume = rr ? sume1 : sume0;
            const int   mink = rr ? mink1 : mink0;
            const u64   a0 = rr ? ac10 : ac00, a1 = rr ? ac11 : ac01;
            const u64   a2 = rr ? ac12 : ac02, a3 = rr ? ac13 : ac03;
            const int   pos = blockIdx.x * ROWS + row;
            const float inv = 1.0f / sume;
            float x0, x1, x2, x3, x4, x5, x6, x7;
            upk2(a0, x0, x1); upk2(a1, x2, x3); upk2(a2, x4, x5); upk2(a3, x6, x7);
            float4* sp = reinterpret_cast<float4*>(out_soft + (size_t)pos * ZC + (size_t)l * CDIM);
            sp[0] = make_float4(x0 * inv, x1 * inv, x2 * inv, x3 * inv);
            sp[1] = make_float4(x4 * inv, x5 * inv, x6 * inv, x7 * inv);
            if (out_hard) {
                const float4* cw = reinterpret_cast<const float4*>(codes) + ((size_t)l * KCODES + mink) * 2;
                float4* hp = reinterpret_cast<float4*>(out_hard + (size_t)pos * ZC + (size_t)l * CDIM);
                hp[0] = cw[0];
                hp[1] = cw[1];
            }
            if (out_idx) out_idx[(size_t)pos * LDIM + l] = (float)mink;
        }
    }
}

extern "C" void kernel_launch(void* const* d_in, const int* in_sizes, int n_in,
                              void* d_out, int out_size) {
    const float* z     = (const float*)d_in[0];
    const float* codes = (const float*)d_in[1];
    float* out = (float*)d_out;

    const long long softN = (long long)NPOS * ZC;
    const long long idxN  = (long long)NPOS * LDIM;
    float* soft = out;
    float* hard = ((long long)out_size >= 2 * softN) ? out + softN : nullptr;
    float* idxo = ((long long)out_size >= 2 * softN + idxN) ? out + 2 * softN : nullptr;

    dim3 grid(NPOS / ROWS, LDIM);
    sth_mma<<<grid, 256>>>(z, codes, soft, hard, idxo);
}

// round 10
// speedup vs baseline: 1.3495x; 1.3495x over previous
#include <cuda_runtime.h>
#include <cuda_bf16.h>
#include <cstring>

#define ZC 128
#define LDIM 16
#define KCODES 256
#define CDIM 8
#define NPOS 32768
#define WHPLANE 4096
#define ROWS 128           // positions per block

typedef unsigned long long u64;
typedef unsigned int u32;

#define S1f  2.0813689810056077f      // log2(e)^2
#define M2S1f (-4.1627379620112154f)  // -2*log2(e)^2

__device__ __forceinline__ u64 pk2u(u32 lo, u32 hi) {
    u64 r; asm("mov.b64 %0, {%1, %2};" : "=l"(r) : "r"(lo), "r"(hi)); return r;
}
__device__ __forceinline__ void upk2u(u64 p, u32& lo, u32& hi) {
    asm("mov.b64 {%0, %1}, %2;" : "=r"(lo), "=r"(hi) : "l"(p));
}
__device__ __forceinline__ float sqrt_ap(float x) {
    float r; asm("sqrt.approx.f32 %0, %1;" : "=f"(r) : "f"(x)); return r;
}
__device__ __forceinline__ float ex2_ap(float x) {
    float r; asm("ex2.approx.f32 %0, %1;" : "=f"(r) : "f"(x)); return r;
}
__device__ __forceinline__ u32 cat16(__nv_bfloat16 lo, __nv_bfloat16 hi) {
    unsigned short a, b; memcpy(&a, &lo, 2); memcpy(&b, &hi, 2);
    return (u32)a | ((u32)b << 16);
}
// pack two f32 into bf16x2: lo -> low half, hi -> high half
__device__ __forceinline__ u32 pkbf(float lo, float hi) {
    u32 r; asm("cvt.rn.bf16x2.f32 %0, %1, %2;" : "=r"(r) : "f"(hi), "f"(lo)); return r;
}
// 3-way bf16 split: x ~= b0+b1+b2, residual ~2^-27|x|
__device__ __forceinline__ void split3(float x, __nv_bfloat16& b0, __nv_bfloat16& b1, __nv_bfloat16& b2) {
    b0 = __float2bfloat16(x);
    float r = x - __bfloat162float(b0);
    b1 = __float2bfloat16(r);
    r = r - __bfloat162float(b1);
    b2 = __float2bfloat16(r);
}
// mma.sync m16n8k16 row.col bf16 -> f32, accumulate in place
__device__ __forceinline__ void hmma(float& d0, float& d1, float& d2, float& d3,
                                     u32 a0, u32 a1, u32 a2, u32 a3, u32 b0, u32 b1) {
    asm volatile(
        "mma.sync.aligned.m16n8k16.row.col.f32.bf16.bf16.f32 "
        "{%0,%1,%2,%3}, {%4,%5,%6,%7}, {%8,%9}, {%0,%1,%2,%3};"
        : "+f"(d0), "+f"(d1), "+f"(d2), "+f"(d3)
        : "r"(a0), "r"(a1), "r"(a2), "r"(a3), "r"(b0), "r"(b1));
}

// Block: 256 threads, 8 warps, 128 positions x one latent (blockIdx.y).
// GEMM1 (exact split-bf16): G[row,code] dots. Epilogue computes e=exp(-dist)
// in f32 (argmin exact), converts e to split-bf16 P fragments IN REGISTERS
// (D->A fragment layout identity), then GEMM2 accumulates soft = P*C.
__global__ void __launch_bounds__(256)
sth_mma2(const float* __restrict__ z, const float* __restrict__ codes,
         float* __restrict__ out_soft, float* __restrict__ out_hard,
         float* __restrict__ out_idx)
{
    __shared__ u64   sBf[2][KCODES / 8][32];  // GEMM1 B frags [variant][8chunk][lane] 16 KB
    __shared__ u64   sB2[2][KCODES / 16][32]; // GEMM2 B frags [variant][16chunk][lane] 8 KB
    __shared__ u32   sCsp[2][KCODES][4];      // staged split codes (channel pairs)   8 KB
    __shared__ u32   sA[ROWS][3][4];          // A data [row][split][colpair]          6 KB
    __shared__ float sCN[KCODES];             // S1*||c||^2                            1 KB
    __shared__ float sHN[ROWS];               // S1*||h||^2                            0.5 KB

    const int l    = blockIdx.y;
    const int tid  = threadIdx.x;
    const int lane = tid & 31;
    const int wid  = tid >> 5;

    // ---- preamble 1: thread tid owns code k = tid ----
    {
        const float4* cp = reinterpret_cast<const float4*>(codes) + ((size_t)l * KCODES + tid) * 2;
        const float4 ca = cp[0];
        const float4 cb = cp[1];
        float c[8] = {ca.x, ca.y, ca.z, ca.w, cb.x, cb.y, cb.z, cb.w};
        u32 cs0[4], cs1[4], cs2[4];
        float cn = 0.f;
        #pragma unroll
        for (int i = 0; i < 4; i++) {
            __nv_bfloat16 x0, x1, x2, y0, y1, y2;
            split3(c[2*i],   x0, x1, x2);
            split3(c[2*i+1], y0, y1, y2);
            cs0[i] = cat16(x0, y0); cs1[i] = cat16(x1, y1); cs2[i] = cat16(x2, y2);
            cn = fmaf(c[2*i], c[2*i], cn);
            cn = fmaf(c[2*i+1], c[2*i+1], cn);
        }
        sCN[tid] = S1f * cn;
        #pragma unroll
        for (int i = 0; i < 4; i++) {
            sCsp[0][tid][i] = cs0[i];
            sCsp[1][tid][i] = cs1[i];
        }
        // GEMM1 B fragments (code tid -> chunk tid>>3, col-group tid&7)
        const int nc = tid >> 3, cg = tid & 7;
        #pragma unroll
        for (int qq = 0; qq < 4; qq++) {
            sBf[0][nc][cg * 4 + qq] = pk2u(cs0[qq], cs1[qq]);  // [B0|B1]
            sBf[1][nc][cg * 4 + qq] = pk2u(cs0[qq], cs2[qq]);  // [B0|B2]
        }
    }
    if (tid < ROWS) {
        const int pos = blockIdx.x * ROWS + tid;
        const int bb = pos >> 12, wh = pos & 4095;
        const float* zp = z + ((size_t)bb * ZC + (size_t)l * CDIM) * WHPLANE + wh;
        float h[8];
        float hn = 0.f;
        #pragma unroll
        for (int i = 0; i < 8; i++) { h[i] = zp[i * WHPLANE]; hn = fmaf(h[i], h[i], hn); }
        sHN[tid] = S1f * hn;
        #pragma unroll
        for (int i = 0; i < 4; i++) {
            __nv_bfloat16 x0, x1, x2, y0, y1, y2;
            split3(h[2*i],   x0, x1, x2);
            split3(h[2*i+1], y0, y1, y2);
            sA[tid][0][i] = cat16(x0, y0);
            sA[tid][1][i] = cat16(x1, y1);
            sA[tid][2][i] = cat16(x2, y2);
        }
    }
    __syncthreads();

    // ---- preamble 2: build GEMM2 B fragments (4 entries per thread) ----
    // Entry (v, nc, ln): n = ln>>2 (channel), t = ln&3; codes k0 = nc*16+2t.
    // b0 = (C_v[k0][n], C_v[k0+1][n]), b1 = (C_v[k0+8][n], C_v[k0+9][n]).
    #pragma unroll
    for (int e = 0; e < 4; e++) {
        const int idx = tid * 4 + e;
        const int v  = idx >> 9;
        const int rr = idx & 511;
        const int nc = rr >> 5;
        const int ln = rr & 31;
        const int n  = ln >> 2, t = ln & 3;
        const int k0 = nc * 16 + 2 * t;
        const int w  = n >> 1, hsh = (n & 1) * 16;
        const u32 vlo0 = (sCsp[v][k0    ][w] >> hsh) & 0xFFFFu;
        const u32 vlo1 = (sCsp[v][k0 + 1][w] >> hsh) & 0xFFFFu;
        const u32 vhi0 = (sCsp[v][k0 + 8][w] >> hsh) & 0xFFFFu;
        const u32 vhi1 = (sCsp[v][k0 + 9][w] >> hsh) & 0xFFFFu;
        sB2[v][nc][ln] = pk2u(vlo0 | (vlo1 << 16), vhi0 | (vhi1 << 16));
    }
    __syncthreads();

    // ---- per-thread fragment context ----
    const int q  = lane & 3;
    const int r0 = wid * 16 + (lane >> 2);
    const int r1 = r0 + 8;
    const u32 A00 = sA[r0][0][q], A01 = sA[r0][1][q], A02 = sA[r0][2][q];
    const u32 A10 = sA[r1][0][q], A11 = sA[r1][1][q], A12 = sA[r1][2][q];
    const float hn0 = sHN[r0], hn1 = sHN[r1];

    float s0 = 0.f, s1 = 0.f, s2 = 0.f, s3 = 0.f;   // soft D fragment
    float sume0 = 0.f, sume1 = 0.f;
    float mind0 = 3.4e38f, mind1 = 3.4e38f;
    int   mink0 = 0,        mink1 = 0;

    #pragma unroll 2
    for (int nc = 0; nc < KCODES / 16; nc++) {
        u32 b00, b01, b10, b11;
        // GEMM1 lo (codes nc*16 + 0..7)
        upk2u(sBf[0][2 * nc][lane], b00, b01);
        upk2u(sBf[1][2 * nc][lane], b10, b11);
        float g0 = 0.f, g1 = 0.f, g2 = 0.f, g3 = 0.f;
        hmma(g0, g1, g2, g3, A00, A10, A01, A11, b00, b01);
        hmma(g0, g1, g2, g3, A01, A11, A00, A10, b00, b01);
        hmma(g0, g1, g2, g3, A02, A12, A00, A10, b10, b11);
        // GEMM1 hi (codes nc*16 + 8..15)
        upk2u(sBf[0][2 * nc + 1][lane], b00, b01);
        upk2u(sBf[1][2 * nc + 1][lane], b10, b11);
        float f0 = 0.f, f1 = 0.f, f2 = 0.f, f3 = 0.f;
        hmma(f0, f1, f2, f3, A00, A10, A01, A11, b00, b01);
        hmma(f0, f1, f2, f3, A01, A11, A00, A10, b00, b01);
        hmma(f0, f1, f2, f3, A02, A12, A00, A10, b10, b11);

        const int kb = nc * 16 + q * 2;
        const float2 cnl = *reinterpret_cast<const float2*>(&sCN[kb]);
        const float2 cnh = *reinterpret_cast<const float2*>(&sCN[kb + 8]);

        // d2' = S1*||h-c||^2
        const float d00 = fmaf(g0, M2S1f, hn0 + cnl.x);
        const float d01 = fmaf(g1, M2S1f, hn0 + cnl.y);
        const float d10 = fmaf(g2, M2S1f, hn1 + cnl.x);
        const float d11 = fmaf(g3, M2S1f, hn1 + cnl.y);
        const float d08 = fmaf(f0, M2S1f, hn0 + cnh.x);
        const float d09 = fmaf(f1, M2S1f, hn0 + cnh.y);
        const float d18 = fmaf(f2, M2S1f, hn1 + cnh.x);
        const float d19 = fmaf(f3, M2S1f, hn1 + cnh.y);

        // argmin per row (ascending k order within lane)
        bool t;
        t = d00 < mind0; mind0 = fminf(mind0, d00); mink0 = t ? kb     : mink0;
        t = d01 < mind0; mind0 = fminf(mind0, d01); mink0 = t ? kb + 1 : mink0;
        t = d08 < mind0; mind0 = fminf(mind0, d08); mink0 = t ? kb + 8 : mink0;
        t = d09 < mind0; mind0 = fminf(mind0, d09); mink0 = t ? kb + 9 : mink0;
        t = d10 < mind1; mind1 = fminf(mind1, d10); mink1 = t ? kb     : mink1;
        t = d11 < mind1; mind1 = fminf(mind1, d11); mink1 = t ? kb + 1 : mink1;
        t = d18 < mind1; mind1 = fminf(mind1, d18); mink1 = t ? kb + 8 : mink1;
        t = d19 < mind1; mind1 = fminf(mind1, d19); mink1 = t ? kb + 9 : mink1;

        // e = exp(-dist) = 2^(-sqrt(S1*d2))
        const float e00 = ex2_ap(0.0f - sqrt_ap(fabsf(d00)));
        const float e01 = ex2_ap(0.0f - sqrt_ap(fabsf(d01)));
        const float e10 = ex2_ap(0.0f - sqrt_ap(fabsf(d10)));
        const float e11 = ex2_ap(0.0f - sqrt_ap(fabsf(d11)));
        const float e08 = ex2_ap(0.0f - sqrt_ap(fabsf(d08)));
        const float e09 = ex2_ap(0.0f - sqrt_ap(fabsf(d09)));
        const float e18 = ex2_ap(0.0f - sqrt_ap(fabsf(d18)));
        const float e19 = ex2_ap(0.0f - sqrt_ap(fabsf(d19)));
        sume0 += (e00 + e01) + (e08 + e09);
        sume1 += (e10 + e11) + (e18 + e19);

        // P fragments (D->A layout identity), 2-way split
        const u32 p0a0 = pkbf(e00, e01);
        const u32 p0a1 = pkbf(e10, e11);
        const u32 p0a2 = pkbf(e08, e09);
        const u32 p0a3 = pkbf(e18, e19);
        const u32 p1a0 = pkbf(e00 - __uint_as_float(p0a0 << 16), e01 - __uint_as_float(p0a0 & 0xFFFF0000u));
        const u32 p1a1 = pkbf(e10 - __uint_as_float(p0a1 << 16), e11 - __uint_as_float(p0a1 & 0xFFFF0000u));
        const u32 p1a2 = pkbf(e08 - __uint_as_float(p0a2 << 16), e09 - __uint_as_float(p0a2 & 0xFFFF0000u));
        const u32 p1a3 = pkbf(e18 - __uint_as_float(p0a3 << 16), e19 - __uint_as_float(p0a3 & 0xFFFF0000u));

        // GEMM2: soft += P*C  (P0C0 + P1C0 + P0C1; P1C1 ~2^-18 dropped)
        u32 c0b0, c0b1, c1b0, c1b1;
        upk2u(sB2[0][nc][lane], c0b0, c0b1);
        upk2u(sB2[1][nc][lane], c1b0, c1b1);
        hmma(s0, s1, s2, s3, p0a0, p0a1, p0a2, p0a3, c0b0, c0b1);
        hmma(s0, s1, s2, s3, p1a0, p1a1, p1a2, p1a3, c0b0, c0b1);
        hmma(s0, s1, s2, s3, p0a0, p0a1, p0a2, p0a3, c1b0, c1b1);
    }

    // ---- merge sume/argmin across the 4 lanes sharing each row ----
    #pragma unroll
    for (int m = 1; m <= 2; m <<= 1) {
        sume0 += __shfl_xor_sync(0xffffffffu, sume0, m);
        sume1 += __shfl_xor_sync(0xffffffffu, sume1, m);
        {
            const float om = __shfl_xor_sync(0xffffffffu, mind0, m);
            const int   ok = __shfl_xor_sync(0xffffffffu, mink0, m);
            const bool  tt = (om < mind0) || (om == mind0 && ok < mink0);
            mind0 = tt ? om : mind0; mink0 = tt ? ok : mink0;
        }
        {
            const float om = __shfl_xor_sync(0xffffffffu, mind1, m);
            const int   ok = __shfl_xor_sync(0xffffffffu, mink1, m);
            const bool  tt = (om < mind1) || (om == mind1 && ok < mink1);
            mind1 = tt ? om : mind1; mink1 = tt ? ok : mink1;
        }
    }

    // ---- outputs ----
    const float inv0 = 1.0f / sume0;
    const float inv1 = 1.0f / sume1;
    const int pos0 = blockIdx.x * ROWS + r0;
    const int pos1 = blockIdx.x * ROWS + r1;
    // soft: lane holds channels 2q, 2q+1 for rows r0 (s0,s1) and r1 (s2,s3)
    {
        float2* sp0 = reinterpret_cast<float2*>(out_soft + (size_t)pos0 * ZC + (size_t)l * CDIM + 2 * q);
        *sp0 = make_float2(s0 * inv0, s1 * inv0);
        float2* sp1 = reinterpret_cast<float2*>(out_soft + (size_t)pos1 * ZC + (size_t)l * CDIM + 2 * q);
        *sp1 = make_float2(s2 * inv1, s3 * inv1);
    }
    if (q == 0) {
        if (out_hard) {
            const float4* cw0 = reinterpret_cast<const float4*>(codes) + ((size_t)l * KCODES + mink0) * 2;
            const float4* cw1 = reinterpret_cast<const float4*>(codes) + ((size_t)l * KCODES + mink1) * 2;
            float4* hp0 = reinterpret_cast<float4*>(out_hard + (size_t)pos0 * ZC + (size_t)l * CDIM);
            float4* hp1 = reinterpret_cast<float4*>(out_hard + (size_t)pos1 * ZC + (size_t)l * CDIM);
            hp0[0] = cw0[0]; hp0[1] = cw0[1];
            hp1[0] = cw1[0]; hp1[1] = cw1[1];
        }
        if (out_idx) {
            out_idx[(size_t)pos0 * LDIM + l] = (float)mink0;
            out_idx[(size_t)pos1 * LDIM + l] = (float)mink1;
        }
    }
}

extern "C" void kernel_launch(void* const* d_in, const int* in_sizes, int n_in,
                              void* d_out, int out_size) {
    const float* z     = (const float*)d_in[0];
    const float* codes = (const float*)d_in[1];
    float* out = (float*)d_out;

    const long long softN = (long long)NPOS * ZC;
    const long long idxN  = (long long)NPOS * LDIM;
    float* soft = out;
    float* hard = ((long long)out_size >= 2 * softN) ? out + softN : nullptr;
    float* idxo = ((long long)out_size >= 2 * softN + idxN) ? out + 2 * softN : nullptr;

    dim3 grid(NPOS / ROWS, LDIM);
    sth_mma2<<<grid, 256>>>(z, codes, soft, hard, idxo);
}

// round 11
// speedup vs baseline: 1.4654x; 1.0859x over previous
#include <cuda_runtime.h>
#include <cuda_bf16.h>
#include <cstring>

#define ZC 128
#define LDIM 16
#define KCODES 256
#define CDIM 8
#define NPOS 32768
#define WHPLANE 4096
#define RBLK 256           // positions per block (2 row-tiles of 128)

typedef unsigned long long u64;
typedef unsigned int u32;
typedef unsigned short u16;

#define S1f  2.0813689810056077f      // log2(e)^2
#define M2S1f (-4.1627379620112154f)  // -2*log2(e)^2

__device__ __forceinline__ float sqrt_ap(float x) {
    float r; asm("sqrt.approx.f32 %0, %1;" : "=f"(r) : "f"(x)); return r;
}
__device__ __forceinline__ float ex2_ap(float x) {
    float r; asm("ex2.approx.f32 %0, %1;" : "=f"(r) : "f"(x)); return r;
}
__device__ __forceinline__ u32 cat16(__nv_bfloat16 lo, __nv_bfloat16 hi) {
    u16 a, b; memcpy(&a, &lo, 2); memcpy(&b, &hi, 2);
    return (u32)a | ((u32)b << 16);
}
// pack two f32 into bf16x2: lo -> low half, hi -> high half
__device__ __forceinline__ u32 pkbf(float lo, float hi) {
    u32 r; asm("cvt.rn.bf16x2.f32 %0, %1, %2;" : "=r"(r) : "f"(hi), "f"(lo)); return r;
}
// 3-way bf16 split: x ~= b0+b1+b2, residual ~2^-27|x|
__device__ __forceinline__ void split3(float x, __nv_bfloat16& b0, __nv_bfloat16& b1, __nv_bfloat16& b2) {
    b0 = __float2bfloat16(x);
    float r = x - __bfloat162float(b0);
    b1 = __float2bfloat16(r);
    r = r - __bfloat162float(b1);
    b2 = __float2bfloat16(r);
}
// mma.sync m16n8k16 row.col bf16 -> f32, accumulate in place
__device__ __forceinline__ void hmma(float& d0, float& d1, float& d2, float& d3,
                                     u32 a0, u32 a1, u32 a2, u32 a3, u32 b0, u32 b1) {
    asm volatile(
        "mma.sync.aligned.m16n8k16.row.col.f32.bf16.bf16.f32 "
        "{%0,%1,%2,%3}, {%4,%5,%6,%7}, {%8,%9}, {%0,%1,%2,%3};"
        : "+f"(d0), "+f"(d1), "+f"(d2), "+f"(d3)
        : "r"(a0), "r"(a1), "r"(a2), "r"(a3), "r"(b0), "r"(b1));
}

// Block: 256 threads, 8 warps, 256 positions (2 row-tiles) x one latent.
// GEMM1 (exact split-bf16) -> dots; f32 softmin epilogue; GEMM2 (P0C0+P1C0+P0C1)
// accumulates soft from in-register P fragments. Both variants of every smem
// fragment are packed in one uint4 (1 LDS.128 each).
__global__ void __launch_bounds__(256)
sth_mma3(const float* __restrict__ z, const float* __restrict__ codes,
         float* __restrict__ out_soft, float* __restrict__ out_hard,
         float* __restrict__ out_idx)
{
    __shared__ uint4  sBf[KCODES / 8][32];   // GEMM1 B: (cs0,cs1,cs0,cs2)  16 KB
    __shared__ uint4  sB2[KCODES / 16][32];  // GEMM2 B: (v0lo,v0hi,v1lo,v1hi) 8 KB
    __shared__ u32    sA[RBLK][3][4];        // A rows [row][split][colpair] 12 KB
    __shared__ float4 sCN4[KCODES / 16][4];  // norms permuted (kb,kb+1,kb+8,kb+9) 1 KB
    __shared__ float  sHN[RBLK];             // S1*||h||^2                   1 KB

    const int l    = blockIdx.y;
    const int tid  = threadIdx.x;
    const int lane = tid & 31;
    const int wid  = tid >> 5;

    // ---- preamble 1: thread tid owns code k = tid ----
    {
        const float4* cp = reinterpret_cast<const float4*>(codes) + ((size_t)l * KCODES + tid) * 2;
        const float4 ca = cp[0];
        const float4 cb = cp[1];
        float c[8] = {ca.x, ca.y, ca.z, ca.w, cb.x, cb.y, cb.z, cb.w};
        u32 cs0[4], cs1[4], cs2[4];
        float cn = 0.f;
        #pragma unroll
        for (int i = 0; i < 4; i++) {
            __nv_bfloat16 x0, x1, x2, y0, y1, y2;
            split3(c[2*i],   x0, x1, x2);
            split3(c[2*i+1], y0, y1, y2);
            cs0[i] = cat16(x0, y0); cs1[i] = cat16(x1, y1); cs2[i] = cat16(x2, y2);
            cn = fmaf(c[2*i], c[2*i], cn);
            cn = fmaf(c[2*i+1], c[2*i+1], cn);
        }
        // permuted norm scatter: chunk nc=k>>4, j=k&15 -> sCN4[nc][(j>>1)&3][elem]
        const int nc = tid >> 4, j = tid & 15;
        reinterpret_cast<float*>(&sCN4[nc][(j >> 1) & 3])[(j & 1) + ((j >> 3) << 1)] = S1f * cn;
        // GEMM1 B fragments (sub-chunk tid>>3, col-group tid&7), both variants packed
        const int nc2 = tid >> 3, cg = tid & 7;
        #pragma unroll
        for (int qq = 0; qq < 4; qq++)
            sBf[nc2][cg * 4 + qq] = make_uint4(cs0[qq], cs1[qq], cs0[qq], cs2[qq]);
        // GEMM2 B fragments: direct 16-bit scatter (no staging pass).
        // Entry [nc][n*4+t]: v0 halves at u16 elems {0..3}, v1 at {4..7};
        // code k=nc*16+j lands at t=(j&7)>>1, elem e0=(j>=8?2:0)+(j&1).
        const int t  = (j & 7) >> 1;
        const int e0 = ((j >> 3) << 1) + (j & 1);
        #pragma unroll
        for (int n = 0; n < 8; n++) {
            u16* us = reinterpret_cast<u16*>(&sB2[nc][n * 4 + t]);
            const int sh = (n & 1) * 16;
            us[e0]     = (u16)(cs0[n >> 1] >> sh);
            us[4 + e0] = (u16)(cs1[n >> 1] >> sh);
        }
    }
    // ---- preamble 2: thread tid owns global row tid (256 rows) ----
    {
        const int pos = blockIdx.x * RBLK + tid;
        const int bb = pos >> 12, wh = pos & 4095;
        const float* zp = z + ((size_t)bb * ZC + (size_t)l * CDIM) * WHPLANE + wh;
        float h[8];
        float hn = 0.f;
        #pragma unroll
        for (int i = 0; i < 8; i++) { h[i] = zp[i * WHPLANE]; hn = fmaf(h[i], h[i], hn); }
        sHN[tid] = S1f * hn;
        #pragma unroll
        for (int i = 0; i < 4; i++) {
            __nv_bfloat16 x0, x1, x2, y0, y1, y2;
            split3(h[2*i],   x0, x1, x2);
            split3(h[2*i+1], y0, y1, y2);
            sA[tid][0][i] = cat16(x0, y0);
            sA[tid][1][i] = cat16(x1, y1);
            sA[tid][2][i] = cat16(x2, y2);
        }
    }
    __syncthreads();

    // ---- fragment context: 2 row-tiles, rows r0/r1 per tile ----
    const int q  = lane & 3;
    const int br = wid * 16 + (lane >> 2);
    u32 Af[2][6];   // per rt: {A00,A10,A01,A11,A02,A12}
    float hnr[2][2];
    #pragma unroll
    for (int rt = 0; rt < 2; rt++) {
        const int r0 = rt * 128 + br, r1 = r0 + 8;
        Af[rt][0] = sA[r0][0][q]; Af[rt][1] = sA[r1][0][q];
        Af[rt][2] = sA[r0][1][q]; Af[rt][3] = sA[r1][1][q];
        Af[rt][4] = sA[r0][2][q]; Af[rt][5] = sA[r1][2][q];
        hnr[rt][0] = sHN[r0];
        hnr[rt][1] = sHN[r1];
    }

    float sf[2][4] = {{0.f,0.f,0.f,0.f},{0.f,0.f,0.f,0.f}};
    float sume[2][2] = {{0.f,0.f},{0.f,0.f}};
    float mind[2][2] = {{3.4e38f,3.4e38f},{3.4e38f,3.4e38f}};
    int   mink[2][2] = {{0,0},{0,0}};

    for (int nc = 0; nc < KCODES / 16; nc++) {
        const uint4 B1a = sBf[2 * nc][lane];
        const uint4 B1b = sBf[2 * nc + 1][lane];
        const uint4 B2v = sB2[nc][lane];
        const float4 cn4 = sCN4[nc][q];
        const int kb = nc * 16 + 2 * q;

        #pragma unroll
        for (int rt = 0; rt < 2; rt++) {
            const u32 A00 = Af[rt][0], A10 = Af[rt][1];
            const u32 A01 = Af[rt][2], A11 = Af[rt][3];
            const u32 A02 = Af[rt][4], A12 = Af[rt][5];
            const float hn0 = hnr[rt][0], hn1 = hnr[rt][1];

            float g0 = 0.f, g1 = 0.f, g2 = 0.f, g3 = 0.f;
            hmma(g0, g1, g2, g3, A00, A10, A01, A11, B1a.x, B1a.y);
            hmma(g0, g1, g2, g3, A01, A11, A00, A10, B1a.x, B1a.y);
            hmma(g0, g1, g2, g3, A02, A12, A00, A10, B1a.z, B1a.w);
            float f0 = 0.f, f1 = 0.f, f2 = 0.f, f3 = 0.f;
            hmma(f0, f1, f2, f3, A00, A10, A01, A11, B1b.x, B1b.y);
            hmma(f0, f1, f2, f3, A01, A11, A00, A10, B1b.x, B1b.y);
            hmma(f0, f1, f2, f3, A02, A12, A00, A10, B1b.z, B1b.w);

            const float d00 = fmaf(g0, M2S1f, hn0 + cn4.x);
            const float d01 = fmaf(g1, M2S1f, hn0 + cn4.y);
            const float d10 = fmaf(g2, M2S1f, hn1 + cn4.x);
            const float d11 = fmaf(g3, M2S1f, hn1 + cn4.y);
            const float d08 = fmaf(f0, M2S1f, hn0 + cn4.z);
            const float d09 = fmaf(f1, M2S1f, hn0 + cn4.w);
            const float d18 = fmaf(f2, M2S1f, hn1 + cn4.z);
            const float d19 = fmaf(f3, M2S1f, hn1 + cn4.w);

            bool t;
            t = d00 < mind[rt][0]; mind[rt][0] = fminf(mind[rt][0], d00); mink[rt][0] = t ? kb     : mink[rt][0];
            t = d01 < mind[rt][0]; mind[rt][0] = fminf(mind[rt][0], d01); mink[rt][0] = t ? kb + 1 : mink[rt][0];
            t = d08 < mind[rt][0]; mind[rt][0] = fminf(mind[rt][0], d08); mink[rt][0] = t ? kb + 8 : mink[rt][0];
            t = d09 < mind[rt][0]; mind[rt][0] = fminf(mind[rt][0], d09); mink[rt][0] = t ? kb + 9 : mink[rt][0];
            t = d10 < mind[rt][1]; mind[rt][1] = fminf(mind[rt][1], d10); mink[rt][1] = t ? kb     : mink[rt][1];
            t = d11 < mind[rt][1]; mind[rt][1] = fminf(mind[rt][1], d11); mink[rt][1] = t ? kb + 1 : mink[rt][1];
            t = d18 < mind[rt][1]; mind[rt][1] = fminf(mind[rt][1], d18); mink[rt][1] = t ? kb + 8 : mink[rt][1];
            t = d19 < mind[rt][1]; mind[rt][1] = fminf(mind[rt][1], d19); mink[rt][1] = t ? kb + 9 : mink[rt][1];

            const float e00 = ex2_ap(0.0f - sqrt_ap(fabsf(d00)));
            const float e01 = ex2_ap(0.0f - sqrt_ap(fabsf(d01)));
            const float e10 = ex2_ap(0.0f - sqrt_ap(fabsf(d10)));
            const float e11 = ex2_ap(0.0f - sqrt_ap(fabsf(d11)));
            const float e08 = ex2_ap(0.0f - sqrt_ap(fabsf(d08)));
            const float e09 = ex2_ap(0.0f - sqrt_ap(fabsf(d09)));
            const float e18 = ex2_ap(0.0f - sqrt_ap(fabsf(d18)));
            const float e19 = ex2_ap(0.0f - sqrt_ap(fabsf(d19)));
            sume[rt][0] += (e00 + e01) + (e08 + e09);
            sume[rt][1] += (e10 + e11) + (e18 + e19);

            // P fragments (D->A layout identity), 2-way split
            const u32 p0a0 = pkbf(e00, e01);
            const u32 p0a1 = pkbf(e10, e11);
            const u32 p0a2 = pkbf(e08, e09);
            const u32 p0a3 = pkbf(e18, e19);
            const u32 p1a0 = pkbf(e00 - __uint_as_float(p0a0 << 16), e01 - __uint_as_float(p0a0 & 0xFFFF0000u));
            const u32 p1a1 = pkbf(e10 - __uint_as_float(p0a1 << 16), e11 - __uint_as_float(p0a1 & 0xFFFF0000u));
            const u32 p1a2 = pkbf(e08 - __uint_as_float(p0a2 << 16), e09 - __uint_as_float(p0a2 & 0xFFFF0000u));
            const u32 p1a3 = pkbf(e18 - __uint_as_float(p0a3 << 16), e19 - __uint_as_float(p0a3 & 0xFFFF0000u));

            hmma(sf[rt][0], sf[rt][1], sf[rt][2], sf[rt][3], p0a0, p0a1, p0a2, p0a3, B2v.x, B2v.y);
            hmma(sf[rt][0], sf[rt][1], sf[rt][2], sf[rt][3], p1a0, p1a1, p1a2, p1a3, B2v.x, B2v.y);
            hmma(sf[rt][0], sf[rt][1], sf[rt][2], sf[rt][3], p0a0, p0a1, p0a2, p0a3, B2v.z, B2v.w);
        }
    }

    // ---- merge sume/argmin across the 4 lanes sharing each row ----
    #pragma unroll
    for (int rt = 0; rt < 2; rt++) {
        #pragma unroll
        for (int rr = 0; rr < 2; rr++) {
            #pragma unroll
            for (int m = 1; m <= 2; m <<= 1) {
                sume[rt][rr] += __shfl_xor_sync(0xffffffffu, sume[rt][rr], m);
                const float om = __shfl_xor_sync(0xffffffffu, mind[rt][rr], m);
                const int   ok = __shfl_xor_sync(0xffffffffu, mink[rt][rr], m);
                const bool  tt = (om < mind[rt][rr]) || (om == mind[rt][rr] && ok < mink[rt][rr]);
                mind[rt][rr] = tt ? om : mind[rt][rr];
                mink[rt][rr] = tt ? ok : mink[rt][rr];
            }
        }
    }

    // ---- outputs: 4 rows per lane-quad ----
    #pragma unroll
    for (int rt = 0; rt < 2; rt++) {
        const float inv0 = 1.0f / sume[rt][0];
        const float inv1 = 1.0f / sume[rt][1];
        const int pos0 = blockIdx.x * RBLK + rt * 128 + br;
        const int pos1 = pos0 + 8;
        float2* sp0 = reinterpret_cast<float2*>(out_soft + (size_t)pos0 * ZC + (size_t)l * CDIM + 2 * q);
        *sp0 = make_float2(sf[rt][0] * inv0, sf[rt][1] * inv0);
        float2* sp1 = reinterpret_cast<float2*>(out_soft + (size_t)pos1 * ZC + (size_t)l * CDIM + 2 * q);
        *sp1 = make_float2(sf[rt][2] * inv1, sf[rt][3] * inv1);
        if (q == 0) {
            if (out_hard) {
                const float4* cw0 = reinterpret_cast<const float4*>(codes) + ((size_t)l * KCODES + mink[rt][0]) * 2;
                const float4* cw1 = reinterpret_cast<const float4*>(codes) + ((size_t)l * KCODES + mink[rt][1]) * 2;
                float4* hp0 = reinterpret_cast<float4*>(out_hard + (size_t)pos0 * ZC + (size_t)l * CDIM);
                float4* hp1 = reinterpret_cast<float4*>(out_hard + (size_t)pos1 * ZC + (size_t)l * CDIM);
                hp0[0] = cw0[0]; hp0[1] = cw0[1];
                hp1[0] = cw1[0]; hp1[1] = cw1[1];
            }
            if (out_idx) {
                out_idx[(size_t)pos0 * LDIM + l] = (float)mink[rt][0];
                out_idx[(size_t)pos1 * LDIM + l] = (float)mink[rt][1];
            }
        }
    }
}

extern "C" void kernel_launch(void* const* d_in, const int* in_sizes, int n_in,
                              void* d_out, int out_size) {
    const float* z     = (const float*)d_in[0];
    const float* codes = (const float*)d_in[1];
    float* out = (float*)d_out;

    const long long softN = (long long)NPOS * ZC;
    const long long idxN  = (long long)NPOS * LDIM;
    float* soft = out;
    float* hard = ((long long)out_size >= 2 * softN) ? out + softN : nullptr;
    float* idxo = ((long long)out_size >= 2 * softN + idxN) ? out + 2 * softN : nullptr;

    dim3 grid(NPOS / RBLK, LDIM);
    sth_mma3<<<grid, 256>>>(z, codes, soft, hard, idxo);
}